// round 17
// baseline (speedup 1.0000x reference)
#include <cuda_runtime.h>
#include <cuda_fp16.h>
#include <stdint.h>

// ---------------- problem constants ----------------
constexpr int B = 2, H = 16, S = 2048, D = 64;
constexpr int BH = B * H;
// fold 1/T and log2(e) into Q so exp(score) == exp2(qk)
constexpr float SCALE = 1.4426950408889634f / 32.0f;

constexpr int QT = 256;           // query rows per CTA (two 128-row halves A,B)
constexpr int NT = 128;           // keys per tile
constexpr int NTILES = S / NT;    // 16
constexpr int THREADS = 256;      // 8 warps; warp w owns rows 16w..16w+15 of each half

// smem: K/V tiles, rows of 64 fp16 padded to 72 (144B) -> conflict-free ldmatrix
constexpr int RSB = 144;
constexpr int TILE_BYTES = 128 * RSB;   // 18432

constexpr int SM_K0   = 0;
constexpr int SM_K1   = SM_K0 + TILE_BYTES;
constexpr int SM_V0   = SM_K1 + TILE_BYTES;
constexpr int SM_V1   = SM_V0 + TILE_BYTES;
constexpr int SM_BIAS = SM_V1 + TILE_BYTES;      // 2048 fp32 (8KB)
constexpr int SMEM_SZ = SM_BIAS + S * 4;         // 81920 B -> 2 CTAs/SM

constexpr uint32_t ONES2 = 0x3C003C00u;          // half2(1,1)

// ---------------- device fp16 copies (K/V only) ----------------
__device__ __half g_k16[(size_t)BH * S * D];
__device__ __half g_v16[(size_t)BH * S * D];

// ---------------- helpers ----------------
__device__ __forceinline__ uint32_t su32(const void* p) {
    uint32_t a;
    asm("{ .reg .u64 t; cvta.to.shared.u64 t, %1; cvt.u32.u64 %0, t; }" : "=r"(a) : "l"(p));
    return a;
}
__device__ __forceinline__ void cpa16(uint32_t d, const void* s) {
    asm volatile("cp.async.cg.shared.global [%0], [%1], 16;" :: "r"(d), "l"(s));
}
#define CP_COMMIT() asm volatile("cp.async.commit_group;" ::: "memory")
#define CP_WAIT0()  asm volatile("cp.async.wait_group 0;" ::: "memory")

#define LDSM4(r0, r1, r2, r3, a) \
    asm volatile("ldmatrix.sync.aligned.m8n8.x4.shared.b16 {%0,%1,%2,%3}, [%4];" \
                 : "=r"(r0), "=r"(r1), "=r"(r2), "=r"(r3) : "r"(a))
#define LDSM4T(r0, r1, r2, r3, a) \
    asm volatile("ldmatrix.sync.aligned.m8n8.x4.trans.shared.b16 {%0,%1,%2,%3}, [%4];" \
                 : "=r"(r0), "=r"(r1), "=r"(r2), "=r"(r3) : "r"(a))

__device__ __forceinline__ void mma_f16(float4& c, const uint32_t a[4],
                                        uint32_t b0, uint32_t b1) {
    asm volatile(
        "mma.sync.aligned.m16n8k16.row.col.f32.f16.f16.f32 "
        "{%0,%1,%2,%3}, {%4,%5,%6,%7}, {%8,%9}, {%0,%1,%2,%3};"
        : "+f"(c.x), "+f"(c.y), "+f"(c.z), "+f"(c.w)
        : "r"(a[0]), "r"(a[1]), "r"(a[2]), "r"(a[3]), "r"(b0), "r"(b1));
}
__device__ __forceinline__ uint32_t packh2(float a, float b) {
    __half2 h = __floats2half2_rn(a, b);
    return *(uint32_t*)&h;
}
__device__ __forceinline__ float2 unpackh2(uint32_t u) {
    return __half22float2(*(__half2*)&u);
}
// exp2 of a (bias-preadded) score pair; returns packed fp16x2
__device__ __forceinline__ uint32_t exp2pair(float a, float b) {
    __half2 h = __floats2half2_rn(a, b);
    h = h2exp2(h);
    return *(uint32_t*)&h;
}
__device__ __forceinline__ float2 shfl_xor_f2(float2 v, int m) {
    v.x = __shfl_xor_sync(0xffffffffu, v.x, m);
    v.y = __shfl_xor_sync(0xffffffffu, v.y, m);
    return v;
}
__device__ __forceinline__ void quad_transpose_f2(float2 a[4], int q) {
    {
        float2 v = (q & 1) ? a[0] : a[1];
        v = shfl_xor_f2(v, 1);
        if (q & 1) a[0] = v; else a[1] = v;
        float2 u = (q & 1) ? a[2] : a[3];
        u = shfl_xor_f2(u, 1);
        if (q & 1) a[2] = u; else a[3] = u;
    }
    {
        float2 v = (q & 2) ? a[0] : a[2];
        v = shfl_xor_f2(v, 2);
        if (q & 2) a[0] = v; else a[2] = v;
        float2 u = (q & 2) ? a[1] : a[3];
        u = shfl_xor_f2(u, 2);
        if (q & 2) a[1] = u; else a[3] = u;
    }
}

// 128-row tile -> padded smem (256 threads)
__device__ __forceinline__ void load_tile(uint32_t sdst, const __half* g, int tid) {
#pragma unroll
    for (int it = 0; it < 4; it++) {
        int f = tid + it * THREADS;
        int r = f >> 3, c = f & 7;
        cpa16(sdst + r * RSB + c * 16, g + r * 64 + c * 8);
    }
}

// Q fragments for 16 rows starting at qrow0 (fp32 -> scaled fp16, m16n8k16 A layout)
__device__ __forceinline__ void load_q_frags(uint32_t qa[4][4], const float* qrow0, int L) {
    const float* p0 = qrow0 + (L >> 2) * D + 2 * (L & 3);
    const float* p1 = p0 + 8 * D;
#pragma unroll
    for (int ks = 0; ks < 4; ks++) {
        float2 v00 = *(const float2*)(p0 + 16 * ks);
        float2 v10 = *(const float2*)(p1 + 16 * ks);
        float2 v01 = *(const float2*)(p0 + 16 * ks + 8);
        float2 v11 = *(const float2*)(p1 + 16 * ks + 8);
        qa[ks][0] = packh2(v00.x * SCALE, v00.y * SCALE);
        qa[ks][1] = packh2(v10.x * SCALE, v10.y * SCALE);
        qa[ks][2] = packh2(v01.x * SCALE, v01.y * SCALE);
        qa[ks][3] = packh2(v11.x * SCALE, v11.y * SCALE);
    }
}

// ---------------- prep: fp32 -> fp16 for K and V ----------------
__global__ void prep16(const float* __restrict__ k, const float* __restrict__ v) {
    const int N4 = BH * S * D / 4;
    int i = blockIdx.x * blockDim.x + threadIdx.x;
    if (i >= N4) return;
    float4 b = ((const float4*)k)[i];
    float4 c = ((const float4*)v)[i];
    __half2* k2 = (__half2*)g_k16;
    __half2* v2 = (__half2*)g_v16;
    k2[2 * i]     = __floats2half2_rn(b.x, b.y);
    k2[2 * i + 1] = __floats2half2_rn(b.z, b.w);
    v2[2 * i]     = __floats2half2_rn(c.x, c.y);
    v2[2 * i + 1] = __floats2half2_rn(c.z, c.w);
}

// ---------------- main fused attention (2-loop, bias-in-accum, half2 exp) ----------------
__global__ __launch_bounds__(THREADS, 2)
void attn_main(const float* __restrict__ qf, const int* __restrict__ mask,
               float* __restrict__ out, float* __restrict__ attn)
{
    extern __shared__ char smem[];
    const uint32_t sb = su32(smem);
    const int tid = threadIdx.x;
    const int w   = tid >> 5;
    const int L   = tid & 31;
    const int q_  = L & 3;
    const int bh  = blockIdx.y;
    const int q0  = blockIdx.x * QT;      // A: rows q0.., B: rows q0+128..

    const float* qgA = qf + ((size_t)bh * S + q0) * D;
    const float* qgB = qgA + 128 * D;
    const __half* kg = g_k16 + (size_t)bh * S * D;
    const __half* vg = g_v16 + (size_t)bh * S * D;

    const uint32_t sK[2] = { sb + SM_K0, sb + SM_K1 };
    const uint32_t sV[2] = { sb + SM_V0, sb + SM_V1 };
    float* bf = (float*)(smem + SM_BIAS);

    // prologue: first K/V tile + fp32 bias table (0 / -1e9 per column)
    load_tile(sK[0], kg, tid);
    load_tile(sV[0], vg, tid);
    CP_COMMIT();
    {
        const int* mp = mask + (size_t)(bh >> 4) * S;
        for (int i = tid; i < S; i += THREADS) bf[i] = mp[i] ? 0.0f : -1e9f;
    }

    const uint32_t ka_part = (L & 7) * RSB + (L >> 3) * 16;
    const uint32_t va_part = L * RSB;
    const int      c_base  = 2 * q_;

    // Q fragments for both halves, direct from fp32 global
    uint32_t qaA[4][4], qaB[4][4];
    load_q_frags(qaA, qgA + w * 16 * D, L);
    load_q_frags(qaB, qgB + w * 16 * D, L);

    CP_WAIT0();
    __syncthreads();

    float invA_lo, invA_hi, invB_lo, invB_hi;

    // ===== loop 1: QK_A + QK_B (shared LDSM) -> sums via ones-MMA + PV_A =====
    {
        float4 oc[8];
#pragma unroll
        for (int nb = 0; nb < 8; nb++) oc[nb] = make_float4(0.f, 0.f, 0.f, 0.f);
        float4 saccA[2], saccB[2];
#pragma unroll
        for (int s = 0; s < 2; s++) {
            saccA[s] = make_float4(0.f, 0.f, 0.f, 0.f);
            saccB[s] = make_float4(0.f, 0.f, 0.f, 0.f);
        }

        for (int kt = 0; kt < NTILES; kt++) {
            const int cur = kt & 1;
            if (kt + 1 < NTILES) {
                load_tile(sK[cur ^ 1], kg + (size_t)(kt + 1) * NT * D, tid);
                load_tile(sV[cur ^ 1], vg + (size_t)(kt + 1) * NT * D, tid);
                CP_COMMIT();
            }
            const float* brow = bf + kt * NT;

#pragma unroll
            for (int kb2 = 0; kb2 < 4; kb2++) {
                uint32_t a16A[2][4], a16B[2][4];
#pragma unroll
                for (int i = 0; i < 4; i++) {
                    int nb = kb2 * 4 + i;
                    uint32_t kaddr = sK[cur] + nb * 8 * RSB + ka_part;
                    uint32_t b0, b1, b2, b3, b4, b5, b6, b7;
                    LDSM4(b0, b1, b2, b3, kaddr);
                    LDSM4(b4, b5, b6, b7, kaddr + 64);
                    int c0 = nb * 8 + c_base;
                    float bi0 = brow[c0], bi1 = brow[c0 + 1];
                    // A half (bias folded into accumulator init)
                    {
                        float4 cf = make_float4(bi0, bi1, bi0, bi1);
                        mma_f16(cf, qaA[0], b0, b1);
                        mma_f16(cf, qaA[1], b2, b3);
                        mma_f16(cf, qaA[2], b4, b5);
                        mma_f16(cf, qaA[3], b6, b7);
                        a16A[i >> 1][(i & 1) * 2]     = exp2pair(cf.x, cf.y);
                        a16A[i >> 1][(i & 1) * 2 + 1] = exp2pair(cf.z, cf.w);
                    }
                    // B half
                    {
                        float4 cf = make_float4(bi0, bi1, bi0, bi1);
                        mma_f16(cf, qaB[0], b0, b1);
                        mma_f16(cf, qaB[1], b2, b3);
                        mma_f16(cf, qaB[2], b4, b5);
                        mma_f16(cf, qaB[3], b6, b7);
                        a16B[i >> 1][(i & 1) * 2]     = exp2pair(cf.x, cf.y);
                        a16B[i >> 1][(i & 1) * 2 + 1] = exp2pair(cf.z, cf.w);
                    }
                }
                // row sums via ones-MMA (split accumulators break the RAW chain)
                const int s = kb2 & 1;
                mma_f16(saccA[s], a16A[0], ONES2, ONES2);
                mma_f16(saccA[s], a16A[1], ONES2, ONES2);
                mma_f16(saccB[s], a16B[0], ONES2, ONES2);
                mma_f16(saccB[s], a16B[1], ONES2, ONES2);
                // PV_A
#pragma unroll
                for (int nbo = 0; nbo < 8; nbo++) {
                    uint32_t vaddr = sV[cur] + kb2 * 32 * RSB + nbo * 16 + va_part;
                    uint32_t v0, v1, v2, v3;
                    LDSM4T(v0, v1, v2, v3, vaddr);
                    mma_f16(oc[nbo], a16A[0], v0, v1);
                    mma_f16(oc[nbo], a16A[1], v2, v3);
                }
            }

            if (kt + 1 < NTILES) CP_WAIT0();
            __syncthreads();
        }

        invA_lo = 1.0f / (saccA[0].x + saccA[1].x);
        invA_hi = 1.0f / (saccA[0].z + saccA[1].z);
        invB_lo = 1.0f / (saccB[0].x + saccB[1].x);
        invB_hi = 1.0f / (saccB[0].z + saccB[1].z);

        // O_A write
        float* olo = out + ((size_t)bh * S + q0 + w * 16 + (L >> 2)) * D + c_base;
        float* ohi = olo + 8 * D;
#pragma unroll
        for (int nb = 0; nb < 8; nb++) {
            *(float2*)(olo + nb * 8) = make_float2(oc[nb].x * invA_lo, oc[nb].y * invA_lo);
            *(float2*)(ohi + nb * 8) = make_float2(oc[nb].z * invA_hi, oc[nb].w * invA_hi);
        }
    }

    // ===== loop 2: attn_A + attn_B writes + PV_B (shared K LDSM) =====
    {
        load_tile(sK[0], kg, tid);
        load_tile(sV[0], vg, tid);
        CP_COMMIT();
        CP_WAIT0();
        __syncthreads();

        float4 oc[8];
#pragma unroll
        for (int nb = 0; nb < 8; nb++) oc[nb] = make_float4(0.f, 0.f, 0.f, 0.f);

        float* aAlo = attn + ((size_t)bh * S + q0 + w * 16 + (L >> 2)) * S;
        float* aAhi = aAlo + 8 * (size_t)S;
        float* aBlo = attn + ((size_t)bh * S + q0 + 128 + w * 16 + (L >> 2)) * S;
        float* aBhi = aBlo + 8 * (size_t)S;

        for (int kt = 0; kt < NTILES; kt++) {
            const int cur = kt & 1;
            if (kt + 1 < NTILES) {
                load_tile(sK[cur ^ 1], kg + (size_t)(kt + 1) * NT * D, tid);
                load_tile(sV[cur ^ 1], vg + (size_t)(kt + 1) * NT * D, tid);
                CP_COMMIT();
            }
            const float* brow = bf + kt * NT;

#pragma unroll
            for (int kb2 = 0; kb2 < 4; kb2++) {
                uint32_t a16A[2][4], a16B[2][4];
#pragma unroll
                for (int i = 0; i < 4; i++) {
                    int nb = kb2 * 4 + i;
                    uint32_t kaddr = sK[cur] + nb * 8 * RSB + ka_part;
                    uint32_t b0, b1, b2, b3, b4, b5, b6, b7;
                    LDSM4(b0, b1, b2, b3, kaddr);
                    LDSM4(b4, b5, b6, b7, kaddr + 64);
                    int c0 = nb * 8 + c_base;
                    float bi0 = brow[c0], bi1 = brow[c0 + 1];
                    {
                        float4 cf = make_float4(bi0, bi1, bi0, bi1);
                        mma_f16(cf, qaA[0], b0, b1);
                        mma_f16(cf, qaA[1], b2, b3);
                        mma_f16(cf, qaA[2], b4, b5);
                        mma_f16(cf, qaA[3], b6, b7);
                        a16A[i >> 1][(i & 1) * 2]     = exp2pair(cf.x, cf.y);
                        a16A[i >> 1][(i & 1) * 2 + 1] = exp2pair(cf.z, cf.w);
                    }
                    {
                        float4 cf = make_float4(bi0, bi1, bi0, bi1);
                        mma_f16(cf, qaB[0], b0, b1);
                        mma_f16(cf, qaB[1], b2, b3);
                        mma_f16(cf, qaB[2], b4, b5);
                        mma_f16(cf, qaB[3], b6, b7);
                        a16B[i >> 1][(i & 1) * 2]     = exp2pair(cf.x, cf.y);
                        a16B[i >> 1][(i & 1) * 2 + 1] = exp2pair(cf.z, cf.w);
                    }
                }
                const int col = kt * NT + kb2 * 32 + 8 * q_;
                // attn_A write
                {
                    float2 flo[4], fhi[4];
#pragma unroll
                    for (int i = 0; i < 4; i++) {
                        float2 t = unpackh2(a16A[i >> 1][(i & 1) * 2]);
                        flo[i] = make_float2(t.x * invA_lo, t.y * invA_lo);
                        t = unpackh2(a16A[i >> 1][(i & 1) * 2 + 1]);
                        fhi[i] = make_float2(t.x * invA_hi, t.y * invA_hi);
                    }
                    quad_transpose_f2(flo, q_);
                    quad_transpose_f2(fhi, q_);
                    __stcs((float4*)(aAlo + col),
                           make_float4(flo[0].x, flo[0].y, flo[1].x, flo[1].y));
                    __stcs((float4*)(aAlo + col + 4),
                           make_float4(flo[2].x, flo[2].y, flo[3].x, flo[3].y));
                    __stcs((float4*)(aAhi + col),
                           make_float4(fhi[0].x, fhi[0].y, fhi[1].x, fhi[1].y));
                    __stcs((float4*)(aAhi + col + 4),
                           make_float4(fhi[2].x, fhi[2].y, fhi[3].x, fhi[3].y));
                }
                // attn_B write
                {
                    float2 flo[4], fhi[4];
#pragma unroll
                    for (int i = 0; i < 4; i++) {
                        float2 t = unpackh2(a16B[i >> 1][(i & 1) * 2]);
                        flo[i] = make_float2(t.x * invB_lo, t.y * invB_lo);
                        t = unpackh2(a16B[i >> 1][(i & 1) * 2 + 1]);
                        fhi[i] = make_float2(t.x * invB_hi, t.y * invB_hi);
                    }
                    quad_transpose_f2(flo, q_);
                    quad_transpose_f2(fhi, q_);
                    __stcs((float4*)(aBlo + col),
                           make_float4(flo[0].x, flo[0].y, flo[1].x, flo[1].y));
                    __stcs((float4*)(aBlo + col + 4),
                           make_float4(flo[2].x, flo[2].y, flo[3].x, flo[3].y));
                    __stcs((float4*)(aBhi + col),
                           make_float4(fhi[0].x, fhi[0].y, fhi[1].x, fhi[1].y));
                    __stcs((float4*)(aBhi + col + 4),
                           make_float4(fhi[2].x, fhi[2].y, fhi[3].x, fhi[3].y));
                }
                // PV_B
#pragma unroll
                for (int nbo = 0; nbo < 8; nbo++) {
                    uint32_t vaddr = sV[cur] + kb2 * 32 * RSB + nbo * 16 + va_part;
                    uint32_t v0, v1, v2, v3;
                    LDSM4T(v0, v1, v2, v3, vaddr);
                    mma_f16(oc[nbo], a16B[0], v0, v1);
                    mma_f16(oc[nbo], a16B[1], v2, v3);
                }
            }

            if (kt + 1 < NTILES) CP_WAIT0();
            __syncthreads();
        }

        // O_B write
        float* olo = out + ((size_t)bh * S + q0 + 128 + w * 16 + (L >> 2)) * D + c_base;
        float* ohi = olo + 8 * D;
#pragma unroll
        for (int nb = 0; nb < 8; nb++) {
            *(float2*)(olo + nb * 8) = make_float2(oc[nb].x * invB_lo, oc[nb].y * invB_lo);
            *(float2*)(ohi + nb * 8) = make_float2(oc[nb].z * invB_hi, oc[nb].w * invB_hi);
        }
    }
}

// ---------------- launch ----------------
extern "C" void kernel_launch(void* const* d_in, const int* in_sizes, int n_in,
                              void* d_out, int out_size)
{
    const float* q    = (const float*)d_in[0];
    const float* k    = (const float*)d_in[1];
    const float* v    = (const float*)d_in[2];
    const int*   mask = (const int*)  d_in[3];

    float* out  = (float*)d_out;
    float* attn = out + (size_t)BH * S * D;

    cudaFuncSetAttribute(attn_main, cudaFuncAttributeMaxDynamicSharedMemorySize, SMEM_SZ);

    const int N4 = BH * S * D / 4;
    prep16<<<(N4 + 255) / 256, 256>>>(k, v);
    attn_main<<<dim3(S / QT, BH), THREADS, SMEM_SZ>>>(q, mask, out, attn);
}